// round 12
// baseline (speedup 1.0000x reference)
#include <cuda_runtime.h>
#include <cuda_fp16.h>

#define D 64
#define NU_MAX 100001
#define NI_MAX 200001
#define NMAX (NU_MAX + NI_MAX)
#define PMAX 3200000
#define SCAN_BLK 1024
#define NBINS 128

__device__ __forceinline__ __half2 u2h2(unsigned u) {
    __half2 h; *reinterpret_cast<unsigned*>(&h) = u; return h;
}
__device__ __forceinline__ unsigned h22u(__half2 h) {
    return *reinterpret_cast<unsigned*>(&h);
}

// Scratch (.bss, no allocation). fp16 feature rows: 64 halves = 128B.
__device__ __half g_x0[(size_t)NMAX * D];
__device__ __half g_h1[(size_t)NMAX * D];
__device__ __half g_h2[(size_t)NMAX * D];
__device__ int2   g_edge[2 * PMAX];       // {col, val_bits}; [0,P)=user CSR, [P,2P)=item CSC
__device__ int    g_u_ptr[NU_MAX + 2];
__device__ int    g_i_ptr[NI_MAX + 2];
__device__ int    g_i_work[NI_MAX + 2];
__device__ int    g_cnt[NI_MAX + 2];
__device__ int    g_bsums[512];
__device__ int    g_hist[NBINS];
__device__ int    g_binw[NBINS];
__device__ int    g_perm[NMAX];

// ---------------------------------------------------------------------------
// init: g_x0 = half(concat(ue, ie)); zero item counters + degree histogram.
// ---------------------------------------------------------------------------
__global__ void init_kernel(const float4* __restrict__ ue,
                            const float4* __restrict__ ie,
                            uint4* __restrict__ x0,
                            int* __restrict__ cnt,
                            int* __restrict__ hist,
                            int n_user_u4, int n_total_u4, int n_cnt) {
    int i = blockIdx.x * blockDim.x + threadIdx.x;
    if (i < n_cnt) cnt[i] = 0;
    if (i < NBINS) hist[i] = 0;
    if (i >= n_total_u4) return;
    const float4* src = (i < n_user_u4) ? (ue + (size_t)i * 2)
                                        : (ie + (size_t)(i - n_user_u4) * 2);
    float4 f0 = src[0];
    float4 f1 = src[1];
    uint4 o;
    o.x = h22u(__floats2half2_rn(f0.x, f0.y));
    o.y = h22u(__floats2half2_rn(f0.z, f0.w));
    o.z = h22u(__floats2half2_rn(f1.x, f1.y));
    o.w = h22u(__floats2half2_rn(f1.z, f1.w));
    x0[i] = o;
}

// ---------------------------------------------------------------------------
// u_ptr[r] = lower_bound(row[0:P], r)
// ---------------------------------------------------------------------------
__global__ void build_uptr_kernel(const int* __restrict__ row, int P,
                                  int* __restrict__ uptr, int n_users) {
    int r = blockIdx.x * blockDim.x + threadIdx.x;
    if (r > n_users) return;
    int lo = 0, hi = P;
    while (lo < hi) {
        int mid = (lo + hi) >> 1;
        if (row[mid] < r) lo = mid + 1; else hi = mid;
    }
    uptr[r] = lo;
}

// ---------------------------------------------------------------------------
// count item degrees + pack user-block edges
// ---------------------------------------------------------------------------
__global__ void count_pack_kernel(const int* __restrict__ col,
                                  const float* __restrict__ vals, int P,
                                  int* __restrict__ cnt,
                                  int2* __restrict__ edge, int n_users) {
    int e = blockIdx.x * blockDim.x + threadIdx.x;
    if (e >= P) return;
    int c = col[e];
    atomicAdd(&cnt[c - n_users], 1);
    edge[e] = make_int2(c, __float_as_int(vals[e]));
}

// ---------------------------------------------------------------------------
// exclusive scan -> i_ptr (+P offset)
// ---------------------------------------------------------------------------
__global__ void scan1_kernel(const int* __restrict__ cnt, int* __restrict__ ptr,
                             int* __restrict__ bsums, int n) {
    __shared__ int sh[SCAN_BLK];
    int i = blockIdx.x * SCAN_BLK + threadIdx.x;
    int v = (i < n) ? cnt[i] : 0;
    sh[threadIdx.x] = v;
    __syncthreads();
    for (int off = 1; off < SCAN_BLK; off <<= 1) {
        int t = 0;
        if ((int)threadIdx.x >= off) t = sh[threadIdx.x - off];
        __syncthreads();
        sh[threadIdx.x] += t;
        __syncthreads();
    }
    if (i < n) ptr[i] = sh[threadIdx.x] - v;
    if (threadIdx.x == SCAN_BLK - 1) bsums[blockIdx.x] = sh[SCAN_BLK - 1];
}

__global__ void scan2_kernel(int* __restrict__ bsums, int nb) {
    __shared__ int sh[512];
    int v = ((int)threadIdx.x < nb) ? bsums[threadIdx.x] : 0;
    sh[threadIdx.x] = v;
    __syncthreads();
    for (int off = 1; off < 512; off <<= 1) {
        int t = 0;
        if ((int)threadIdx.x >= off) t = sh[threadIdx.x - off];
        __syncthreads();
        sh[threadIdx.x] += t;
        __syncthreads();
    }
    if ((int)threadIdx.x < nb) bsums[threadIdx.x] = sh[threadIdx.x] - v;
}

__global__ void scan3_kernel(int* __restrict__ ptr, int* __restrict__ work,
                             const int* __restrict__ bsums, int n, int offset) {
    int i = blockIdx.x * blockDim.x + threadIdx.x;
    if (i >= n) return;
    int p = ptr[i] + bsums[i >> 10] + offset;
    ptr[i] = p;
    work[i] = p;
}

// ---------------------------------------------------------------------------
// scatter transpose (item CSC), single 8B store
// ---------------------------------------------------------------------------
__global__ void scatter_kernel(const int* __restrict__ row,
                               const int* __restrict__ col,
                               const float* __restrict__ vals, int P,
                               int* __restrict__ iwork,
                               int2* __restrict__ edge, int n_users) {
    int e = blockIdx.x * blockDim.x + threadIdx.x;
    if (e >= P) return;
    int it = col[e] - n_users;
    int pos = atomicAdd(&iwork[it], 1);   // already offset by P
    edge[pos] = make_int2(row[e], __float_as_int(vals[e]));
}

// ---------------------------------------------------------------------------
// degree counting sort: hist -> scan -> perm (rows grouped by equal degree,
// so the 4 rows sharing a warp in spmm have ~identical trip counts)
// ---------------------------------------------------------------------------
__device__ __forceinline__ int row_deg(int r, const int* uptr, const int* iptr,
                                       int n_users) {
    if (r < n_users) return uptr[r + 1] - uptr[r];
    int ii = r - n_users;
    return iptr[ii + 1] - iptr[ii];
}

__global__ void deg_hist_kernel(const int* __restrict__ uptr,
                                const int* __restrict__ iptr,
                                int* __restrict__ hist,
                                int n_users, int n_total) {
    int r = blockIdx.x * blockDim.x + threadIdx.x;
    if (r >= n_total) return;
    int d = row_deg(r, uptr, iptr, n_users);
    atomicAdd(&hist[min(d, NBINS - 1)], 1);
}

__global__ void hist_scan_kernel(const int* __restrict__ hist,
                                 int* __restrict__ binw) {
    __shared__ int sh[NBINS];
    int t = threadIdx.x;
    int v = hist[t];
    sh[t] = v;
    __syncthreads();
    for (int off = 1; off < NBINS; off <<= 1) {
        int u = 0;
        if (t >= off) u = sh[t - off];
        __syncthreads();
        sh[t] += u;
        __syncthreads();
    }
    binw[t] = sh[t] - v;   // exclusive
}

__global__ void perm_kernel(const int* __restrict__ uptr,
                            const int* __restrict__ iptr,
                            int* __restrict__ binw,
                            int* __restrict__ perm,
                            int n_users, int n_total) {
    int r = blockIdx.x * blockDim.x + threadIdx.x;
    if (r >= n_total) return;
    int d = row_deg(r, uptr, iptr, n_users);
    int pos = atomicAdd(&binw[min(d, NBINS - 1)], 1);
    perm[pos] = r;
}

// ---------------------------------------------------------------------------
// SpMM, 8 lanes per row (4 rows per warp), fp16 gather via LDG.128.
// Row assignment via degree-sorted perm -> near-zero intra-warp divergence.
// ---------------------------------------------------------------------------
#define EDGE_FMA_H(c_, vbits_)  {                                            \
    float v_ = __int_as_float(vbits_);                                       \
    uint4 u_ = x[(size_t)(c_) * 8 + lane];                                   \
    float2 f0_ = __half22float2(u2h2(u_.x));                                 \
    float2 f1_ = __half22float2(u2h2(u_.y));                                 \
    float2 f2_ = __half22float2(u2h2(u_.z));                                 \
    float2 f3_ = __half22float2(u2h2(u_.w));                                 \
    a0 = fmaf(v_, f0_.x, a0); a1 = fmaf(v_, f0_.y, a1);                      \
    a2 = fmaf(v_, f1_.x, a2); a3 = fmaf(v_, f1_.y, a3);                      \
    a4 = fmaf(v_, f2_.x, a4); a5 = fmaf(v_, f2_.y, a5);                      \
    a6 = fmaf(v_, f3_.x, a6); a7 = fmaf(v_, f3_.y, a7); }

__device__ __forceinline__ void row_accum(const uint4* __restrict__ x,
                                          const int2* __restrict__ edge,
                                          int s, int e, int lane,
                                          float& a0, float& a1, float& a2, float& a3,
                                          float& a4, float& a5, float& a6, float& a7) {
    int ei = s;
    if (ei < e && (ei & 1)) {
        int2 p = edge[ei];
        EDGE_FMA_H(p.x, p.y)
        ei++;
    }
    for (; ei + 8 <= e; ei += 8) {
        int4 p0 = *reinterpret_cast<const int4*>(edge + ei);
        int4 p1 = *reinterpret_cast<const int4*>(edge + ei + 2);
        int4 p2 = *reinterpret_cast<const int4*>(edge + ei + 4);
        int4 p3 = *reinterpret_cast<const int4*>(edge + ei + 6);
        EDGE_FMA_H(p0.x, p0.y) EDGE_FMA_H(p0.z, p0.w)
        EDGE_FMA_H(p1.x, p1.y) EDGE_FMA_H(p1.z, p1.w)
        EDGE_FMA_H(p2.x, p2.y) EDGE_FMA_H(p2.z, p2.w)
        EDGE_FMA_H(p3.x, p3.y) EDGE_FMA_H(p3.z, p3.w)
    }
    for (; ei < e; ei++) {
        int2 p = edge[ei];
        EDGE_FMA_H(p.x, p.y)
    }
}

__global__ void spmm_kernel(const uint4* __restrict__ x,
                            uint4* __restrict__ y,
                            const int2* __restrict__ edge,
                            const int* __restrict__ uptr,
                            const int* __restrict__ iptr,
                            const int* __restrict__ perm,
                            int n_users, int n_total) {
    int g = (blockIdx.x * blockDim.x + threadIdx.x) >> 3;   // 8 lanes per row
    int lane = threadIdx.x & 7;
    if (g >= n_total) return;
    int r = perm[g];
    int s, e;
    if (r < n_users) { s = uptr[r]; e = uptr[r + 1]; }
    else { int ii = r - n_users; s = iptr[ii]; e = iptr[ii + 1]; }

    float a0 = 0.f, a1 = 0.f, a2 = 0.f, a3 = 0.f,
          a4 = 0.f, a5 = 0.f, a6 = 0.f, a7 = 0.f;
    row_accum(x, edge, s, e, lane, a0, a1, a2, a3, a4, a5, a6, a7);

    uint4 o;
    o.x = h22u(__floats2half2_rn(a0, a1));
    o.y = h22u(__floats2half2_rn(a2, a3));
    o.z = h22u(__floats2half2_rn(a4, a5));
    o.w = h22u(__floats2half2_rn(a6, a7));
    y[(size_t)r * 8 + lane] = o;
}

// last layer + epilogue: out = (x0 + h1 + h2 + acc) * 0.25  (x0/h1/h2 fp16)
__global__ void spmm_final_kernel(const uint4* __restrict__ x,   // h2
                                  const uint4* __restrict__ x0,
                                  const uint4* __restrict__ h1,
                                  float4* __restrict__ out,
                                  const int2* __restrict__ edge,
                                  const int* __restrict__ uptr,
                                  const int* __restrict__ iptr,
                                  const int* __restrict__ perm,
                                  int n_users, int n_total) {
    int g = (blockIdx.x * blockDim.x + threadIdx.x) >> 3;
    int lane = threadIdx.x & 7;
    if (g >= n_total) return;
    int r = perm[g];
    int s, e;
    if (r < n_users) { s = uptr[r]; e = uptr[r + 1]; }
    else { int ii = r - n_users; s = iptr[ii]; e = iptr[ii + 1]; }

    float a0 = 0.f, a1 = 0.f, a2 = 0.f, a3 = 0.f,
          a4 = 0.f, a5 = 0.f, a6 = 0.f, a7 = 0.f;
    row_accum(x, edge, s, e, lane, a0, a1, a2, a3, a4, a5, a6, a7);

    size_t hoff = (size_t)r * 8 + lane;
    uint4 u0 = x0[hoff];
    uint4 u1 = h1[hoff];
    uint4 u2 = x[hoff];
    float2 z0 = __half22float2(u2h2(u0.x));
    float2 z1 = __half22float2(u2h2(u0.y));
    float2 z2 = __half22float2(u2h2(u0.z));
    float2 z3 = __half22float2(u2h2(u0.w));
    float2 b0 = __half22float2(u2h2(u1.x));
    float2 b1 = __half22float2(u2h2(u1.y));
    float2 b2 = __half22float2(u2h2(u1.z));
    float2 b3 = __half22float2(u2h2(u1.w));
    float2 c0 = __half22float2(u2h2(u2.x));
    float2 c1 = __half22float2(u2h2(u2.y));
    float2 c2 = __half22float2(u2h2(u2.z));
    float2 c3 = __half22float2(u2h2(u2.w));

    float4 r0v, r1v;
    r0v.x = (z0.x + b0.x + c0.x + a0) * 0.25f;
    r0v.y = (z0.y + b0.y + c0.y + a1) * 0.25f;
    r0v.z = (z1.x + b1.x + c1.x + a2) * 0.25f;
    r0v.w = (z1.y + b1.y + c1.y + a3) * 0.25f;
    r1v.x = (z2.x + b2.x + c2.x + a4) * 0.25f;
    r1v.y = (z2.y + b2.y + c2.y + a5) * 0.25f;
    r1v.z = (z3.x + b3.x + c3.x + a6) * 0.25f;
    r1v.w = (z3.y + b3.y + c3.y + a7) * 0.25f;
    size_t foff = (size_t)r * 16 + lane * 2;
    out[foff] = r0v;
    out[foff + 1] = r1v;
}

extern "C" void kernel_launch(void* const* d_in, const int* in_sizes, int n_in,
                              void* d_out, int out_size) {
    const float* user_emb = (const float*)d_in[0];
    const float* item_emb = (const float*)d_in[1];
    const int*   row      = (const int*)d_in[2];
    const int*   col      = (const int*)d_in[3];
    const float* vals     = (const float*)d_in[4];

    const int n_users = in_sizes[0] / D;
    const int n_items = in_sizes[1] / D;
    const int n_total = n_users + n_items;
    const int E       = in_sizes[2];
    const int P       = E / 2;

    float* out = (float*)d_out;

    __half *x0h, *h1, *h2;
    int *u_ptr, *i_ptr, *i_work, *cnt, *bsums, *hist, *binw, *perm;
    int2 *edge;
    cudaGetSymbolAddress((void**)&x0h, g_x0);
    cudaGetSymbolAddress((void**)&h1, g_h1);
    cudaGetSymbolAddress((void**)&h2, g_h2);
    cudaGetSymbolAddress((void**)&edge, g_edge);
    cudaGetSymbolAddress((void**)&u_ptr, g_u_ptr);
    cudaGetSymbolAddress((void**)&i_ptr, g_i_ptr);
    cudaGetSymbolAddress((void**)&i_work, g_i_work);
    cudaGetSymbolAddress((void**)&cnt, g_cnt);
    cudaGetSymbolAddress((void**)&bsums, g_bsums);
    cudaGetSymbolAddress((void**)&hist, g_hist);
    cudaGetSymbolAddress((void**)&binw, g_binw);
    cudaGetSymbolAddress((void**)&perm, g_perm);

    const int TB = 256;
    const int n_u4 = n_total * 8;
    const int n_user_u4 = n_users * 8;
    const int n_cnt = n_items + 1;

    // 1. init: x0h = half(x0); zero counters + histogram
    init_kernel<<<(n_u4 + TB - 1) / TB, TB>>>(
        (const float4*)user_emb, (const float4*)item_emb,
        (uint4*)x0h, cnt, hist, n_user_u4, n_u4, n_cnt);

    // 2. user CSR pointers
    build_uptr_kernel<<<(n_users + 1 + TB - 1) / TB, TB>>>(row, P, u_ptr, n_users);

    // 3. item degrees + pack user edges
    count_pack_kernel<<<(P + TB - 1) / TB, TB>>>(col, vals, P, cnt, edge, n_users);

    // 4. exclusive scan -> i_ptr
    int n_scan = n_cnt;
    int nb = (n_scan + SCAN_BLK - 1) / SCAN_BLK;
    scan1_kernel<<<nb, SCAN_BLK>>>(cnt, i_ptr, bsums, n_scan);
    scan2_kernel<<<1, 512>>>(bsums, nb);
    scan3_kernel<<<(n_scan + TB - 1) / TB, TB>>>(i_ptr, i_work, bsums, n_scan, P);

    // 5. scatter transpose
    scatter_kernel<<<(P + TB - 1) / TB, TB>>>(row, col, vals, P, i_work, edge, n_users);

    // 6. degree counting sort -> perm
    int row_blocks = (n_total + TB - 1) / TB;
    deg_hist_kernel<<<row_blocks, TB>>>(u_ptr, i_ptr, hist, n_users, n_total);
    hist_scan_kernel<<<1, NBINS>>>(hist, binw);
    perm_kernel<<<row_blocks, TB>>>(u_ptr, i_ptr, binw, perm, n_users, n_total);

    // 7-9. three SpMM layers (4 edges/warp-gather, degree-balanced warps)
    int spmm_blocks = (n_total * 8 + TB - 1) / TB;
    spmm_kernel<<<spmm_blocks, TB>>>((const uint4*)x0h, (uint4*)h1,
                                     edge, u_ptr, i_ptr, perm, n_users, n_total);
    spmm_kernel<<<spmm_blocks, TB>>>((const uint4*)h1, (uint4*)h2,
                                     edge, u_ptr, i_ptr, perm, n_users, n_total);
    spmm_final_kernel<<<spmm_blocks, TB>>>((const uint4*)h2, (const uint4*)x0h,
                                           (const uint4*)h1, (float4*)out,
                                           edge, u_ptr, i_ptr, perm, n_users, n_total);
}

// round 13
// speedup vs baseline: 1.3054x; 1.3054x over previous
#include <cuda_runtime.h>
#include <cuda_fp16.h>

#define D 64
#define NU_MAX 100001
#define NI_MAX 200001
#define NMAX (NU_MAX + NI_MAX)
#define PMAX 3200000
#define SCAN_BLK 1024

__device__ __forceinline__ __half2 u2h2(unsigned u) {
    __half2 h; *reinterpret_cast<unsigned*>(&h) = u; return h;
}
__device__ __forceinline__ unsigned h22u(__half2 h) {
    return *reinterpret_cast<unsigned*>(&h);
}

// Scratch (.bss, no allocation). fp16 feature rows: 64 halves = 128B.
__device__ __half g_x0[(size_t)NMAX * D];
__device__ __half g_h1[(size_t)NMAX * D];
__device__ __half g_h2[(size_t)NMAX * D];
__device__ int2   g_tedge[PMAX];          // item CSC packed {col(user), val_bits}
__device__ int    g_u_ptr[NU_MAX + 2];
__device__ int    g_i_ptr[NI_MAX + 2];
__device__ int    g_i_work[NI_MAX + 2];
__device__ int    g_cnt[NI_MAX + 2];
__device__ int    g_bsums[512];

// ---------------------------------------------------------------------------
// zero item-degree counters (must precede the fused counting kernel)
// ---------------------------------------------------------------------------
__global__ void zero_cnt_kernel(int* __restrict__ cnt, int n_cnt) {
    int i = blockIdx.x * blockDim.x + threadIdx.x;
    if (i < n_cnt) cnt[i] = 0;
}

// ---------------------------------------------------------------------------
// fused prep:
//   [0, n_u4)                  : x0h = half(concat(ue, ie))  (DRAM-bound)
//   [n_u4, n_u4+P)             : count item degrees          (L2 atomic-bound)
//   [n_u4+P, n_u4+P+n_users+1) : u_ptr binary search
// ---------------------------------------------------------------------------
__global__ void fused_prep_kernel(const float4* __restrict__ ue,
                                  const float4* __restrict__ ie,
                                  uint4* __restrict__ x0,
                                  const int* __restrict__ row,
                                  const int* __restrict__ col,
                                  int* __restrict__ cnt,
                                  int* __restrict__ uptr,
                                  int n_user_u4, int n_u4, int P, int n_users) {
    int t = blockIdx.x * blockDim.x + threadIdx.x;
    if (t < n_u4) {
        const float4* src = (t < n_user_u4) ? (ue + (size_t)t * 2)
                                            : (ie + (size_t)(t - n_user_u4) * 2);
        float4 f0 = src[0];
        float4 f1 = src[1];
        uint4 o;
        o.x = h22u(__floats2half2_rn(f0.x, f0.y));
        o.y = h22u(__floats2half2_rn(f0.z, f0.w));
        o.z = h22u(__floats2half2_rn(f1.x, f1.y));
        o.w = h22u(__floats2half2_rn(f1.z, f1.w));
        x0[t] = o;
    } else if (t < n_u4 + P) {
        int e = t - n_u4;
        atomicAdd(&cnt[col[e] - n_users], 1);
    } else {
        int r = t - n_u4 - P;
        if (r > n_users) return;
        int lo = 0, hi = P;
        while (lo < hi) {
            int mid = (lo + hi) >> 1;
            if (row[mid] < r) lo = mid + 1; else hi = mid;
        }
        uptr[r] = lo;
    }
}

// ---------------------------------------------------------------------------
// exclusive scan of cnt[0:n] -> i_ptr
// ---------------------------------------------------------------------------
__global__ void scan1_kernel(const int* __restrict__ cnt, int* __restrict__ ptr,
                             int* __restrict__ bsums, int n) {
    __shared__ int sh[SCAN_BLK];
    int i = blockIdx.x * SCAN_BLK + threadIdx.x;
    int v = (i < n) ? cnt[i] : 0;
    sh[threadIdx.x] = v;
    __syncthreads();
    for (int off = 1; off < SCAN_BLK; off <<= 1) {
        int t = 0;
        if ((int)threadIdx.x >= off) t = sh[threadIdx.x - off];
        __syncthreads();
        sh[threadIdx.x] += t;
        __syncthreads();
    }
    if (i < n) ptr[i] = sh[threadIdx.x] - v;
    if (threadIdx.x == SCAN_BLK - 1) bsums[blockIdx.x] = sh[SCAN_BLK - 1];
}

__global__ void scan2_kernel(int* __restrict__ bsums, int nb) {
    __shared__ int sh[512];
    int v = ((int)threadIdx.x < nb) ? bsums[threadIdx.x] : 0;
    sh[threadIdx.x] = v;
    __syncthreads();
    for (int off = 1; off < 512; off <<= 1) {
        int t = 0;
        if ((int)threadIdx.x >= off) t = sh[threadIdx.x - off];
        __syncthreads();
        sh[threadIdx.x] += t;
        __syncthreads();
    }
    if ((int)threadIdx.x < nb) bsums[threadIdx.x] = sh[threadIdx.x] - v;
}

__global__ void scan3_kernel(int* __restrict__ ptr, int* __restrict__ work,
                             const int* __restrict__ bsums, int n) {
    int i = blockIdx.x * blockDim.x + threadIdx.x;
    if (i >= n) return;
    int p = ptr[i] + bsums[i >> 10];
    ptr[i] = p;
    work[i] = p;
}

// ---------------------------------------------------------------------------
// scatter transpose (item CSC), single 8B store
// ---------------------------------------------------------------------------
__global__ void scatter_kernel(const int* __restrict__ row,
                               const int* __restrict__ col,
                               const float* __restrict__ vals, int P,
                               int* __restrict__ iwork,
                               int2* __restrict__ tedge, int n_users) {
    int e = blockIdx.x * blockDim.x + threadIdx.x;
    if (e >= P) return;
    int it = col[e] - n_users;
    int pos = atomicAdd(&iwork[it], 1);
    tedge[pos] = make_int2(row[e], __float_as_int(vals[e]));
}

// ---------------------------------------------------------------------------
// SpMM, 8 lanes per row (4 rows per warp), fp16 gather via LDG.128.
// User rows read col[]/vals[] directly (the original arrays ARE the CSR);
// item rows read the packed int2 CSC. Natural row order (streaming edges).
// ---------------------------------------------------------------------------
#define FMA_ROW(c_, v_)  {                                                   \
    uint4 u_ = x[(size_t)(c_) * 8 + lane];                                   \
    float2 f0_ = __half22float2(u2h2(u_.x));                                 \
    float2 f1_ = __half22float2(u2h2(u_.y));                                 \
    float2 f2_ = __half22float2(u2h2(u_.z));                                 \
    float2 f3_ = __half22float2(u2h2(u_.w));                                 \
    a0 = fmaf(v_, f0_.x, a0); a1 = fmaf(v_, f0_.y, a1);                      \
    a2 = fmaf(v_, f1_.x, a2); a3 = fmaf(v_, f1_.y, a3);                      \
    a4 = fmaf(v_, f2_.x, a4); a5 = fmaf(v_, f2_.y, a5);                      \
    a6 = fmaf(v_, f3_.x, a6); a7 = fmaf(v_, f3_.y, a7); }

// user rows: separate col / val arrays, 16B-aligned paired loads
__device__ __forceinline__ void accum_user(const uint4* __restrict__ x,
                                           const int* __restrict__ col,
                                           const float* __restrict__ val,
                                           int s, int e, int lane,
                                           float& a0, float& a1, float& a2, float& a3,
                                           float& a4, float& a5, float& a6, float& a7) {
    int ei = s;
    while (ei < e && (ei & 3)) {               // align to 16B
        FMA_ROW(col[ei], val[ei])
        ei++;
    }
    for (; ei + 8 <= e; ei += 8) {
        int4   c0 = *reinterpret_cast<const int4*>(col + ei);
        int4   c1 = *reinterpret_cast<const int4*>(col + ei + 4);
        float4 v0 = *reinterpret_cast<const float4*>(val + ei);
        float4 v1 = *reinterpret_cast<const float4*>(val + ei + 4);
        FMA_ROW(c0.x, v0.x) FMA_ROW(c0.y, v0.y)
        FMA_ROW(c0.z, v0.z) FMA_ROW(c0.w, v0.w)
        FMA_ROW(c1.x, v1.x) FMA_ROW(c1.y, v1.y)
        FMA_ROW(c1.z, v1.z) FMA_ROW(c1.w, v1.w)
    }
    for (; ei < e; ei++) {
        FMA_ROW(col[ei], val[ei])
    }
}

// item rows: packed int2 {col, val_bits}
__device__ __forceinline__ void accum_item(const uint4* __restrict__ x,
                                           const int2* __restrict__ tedge,
                                           int s, int e, int lane,
                                           float& a0, float& a1, float& a2, float& a3,
                                           float& a4, float& a5, float& a6, float& a7) {
    int ei = s;
    if (ei < e && (ei & 1)) {
        int2 p = tedge[ei];
        FMA_ROW(p.x, __int_as_float(p.y))
        ei++;
    }
    for (; ei + 8 <= e; ei += 8) {
        int4 p0 = *reinterpret_cast<const int4*>(tedge + ei);
        int4 p1 = *reinterpret_cast<const int4*>(tedge + ei + 2);
        int4 p2 = *reinterpret_cast<const int4*>(tedge + ei + 4);
        int4 p3 = *reinterpret_cast<const int4*>(tedge + ei + 6);
        FMA_ROW(p0.x, __int_as_float(p0.y)) FMA_ROW(p0.z, __int_as_float(p0.w))
        FMA_ROW(p1.x, __int_as_float(p1.y)) FMA_ROW(p1.z, __int_as_float(p1.w))
        FMA_ROW(p2.x, __int_as_float(p2.y)) FMA_ROW(p2.z, __int_as_float(p2.w))
        FMA_ROW(p3.x, __int_as_float(p3.y)) FMA_ROW(p3.z, __int_as_float(p3.w))
    }
    for (; ei < e; ei++) {
        int2 p = tedge[ei];
        FMA_ROW(p.x, __int_as_float(p.y))
    }
}

__global__ void spmm_kernel(const uint4* __restrict__ x,
                            uint4* __restrict__ y,
                            const int* __restrict__ col,
                            const float* __restrict__ val,
                            const int2* __restrict__ tedge,
                            const int* __restrict__ uptr,
                            const int* __restrict__ iptr,
                            int n_users, int n_total) {
    int g = (blockIdx.x * blockDim.x + threadIdx.x) >> 3;   // 8 lanes per row
    int lane = threadIdx.x & 7;
    if (g >= n_total) return;

    float a0 = 0.f, a1 = 0.f, a2 = 0.f, a3 = 0.f,
          a4 = 0.f, a5 = 0.f, a6 = 0.f, a7 = 0.f;
    if (g < n_users) {
        int s = uptr[g], e = uptr[g + 1];
        accum_user(x, col, val, s, e, lane, a0, a1, a2, a3, a4, a5, a6, a7);
    } else {
        int ii = g - n_users;
        int s = iptr[ii], e = iptr[ii + 1];
        accum_item(x, tedge, s, e, lane, a0, a1, a2, a3, a4, a5, a6, a7);
    }

    uint4 o;
    o.x = h22u(__floats2half2_rn(a0, a1));
    o.y = h22u(__floats2half2_rn(a2, a3));
    o.z = h22u(__floats2half2_rn(a4, a5));
    o.w = h22u(__floats2half2_rn(a6, a7));
    y[(size_t)g * 8 + lane] = o;
}

// last layer + epilogue: out = (x0 + h1 + h2 + acc) * 0.25  (x0/h1/h2 fp16)
__global__ void spmm_final_kernel(const uint4* __restrict__ x,   // h2
                                  const uint4* __restrict__ x0,
                                  const uint4* __restrict__ h1,
                                  float4* __restrict__ out,
                                  const int* __restrict__ col,
                                  const float* __restrict__ val,
                                  const int2* __restrict__ tedge,
                                  const int* __restrict__ uptr,
                                  const int* __restrict__ iptr,
                                  int n_users, int n_total) {
    int g = (blockIdx.x * blockDim.x + threadIdx.x) >> 3;
    int lane = threadIdx.x & 7;
    if (g >= n_total) return;

    float a0 = 0.f, a1 = 0.f, a2 = 0.f, a3 = 0.f,
          a4 = 0.f, a5 = 0.f, a6 = 0.f, a7 = 0.f;
    if (g < n_users) {
        int s = uptr[g], e = uptr[g + 1];
        accum_user(x, col, val, s, e, lane, a0, a1, a2, a3, a4, a5, a6, a7);
    } else {
        int ii = g - n_users;
        int s = iptr[ii], e = iptr[ii + 1];
        accum_item(x, tedge, s, e, lane, a0, a1, a2, a3, a4, a5, a6, a7);
    }

    size_t hoff = (size_t)g * 8 + lane;
    uint4 u0 = x0[hoff];
    uint4 u1 = h1[hoff];
    uint4 u2 = x[hoff];
    float2 z0 = __half22float2(u2h2(u0.x));
    float2 z1 = __half22float2(u2h2(u0.y));
    float2 z2 = __half22float2(u2h2(u0.z));
    float2 z3 = __half22float2(u2h2(u0.w));
    float2 b0 = __half22float2(u2h2(u1.x));
    float2 b1 = __half22float2(u2h2(u1.y));
    float2 b2 = __half22float2(u2h2(u1.z));
    float2 b3 = __half22float2(u2h2(u1.w));
    float2 c0 = __half22float2(u2h2(u2.x));
    float2 c1 = __half22float2(u2h2(u2.y));
    float2 c2 = __half22float2(u2h2(u2.z));
    float2 c3 = __half22float2(u2h2(u2.w));

    float4 r0v, r1v;
    r0v.x = (z0.x + b0.x + c0.x + a0) * 0.25f;
    r0v.y = (z0.y + b0.y + c0.y + a1) * 0.25f;
    r0v.z = (z1.x + b1.x + c1.x + a2) * 0.25f;
    r0v.w = (z1.y + b1.y + c1.y + a3) * 0.25f;
    r1v.x = (z2.x + b2.x + c2.x + a4) * 0.25f;
    r1v.y = (z2.y + b2.y + c2.y + a5) * 0.25f;
    r1v.z = (z3.x + b3.x + c3.x + a6) * 0.25f;
    r1v.w = (z3.y + b3.y + c3.y + a7) * 0.25f;
    size_t foff = (size_t)g * 16 + lane * 2;
    out[foff] = r0v;
    out[foff + 1] = r1v;
}

extern "C" void kernel_launch(void* const* d_in, const int* in_sizes, int n_in,
                              void* d_out, int out_size) {
    const float* user_emb = (const float*)d_in[0];
    const float* item_emb = (const float*)d_in[1];
    const int*   row      = (const int*)d_in[2];
    const int*   col      = (const int*)d_in[3];
    const float* vals     = (const float*)d_in[4];

    const int n_users = in_sizes[0] / D;
    const int n_items = in_sizes[1] / D;
    const int n_total = n_users + n_items;
    const int E       = in_sizes[2];
    const int P       = E / 2;

    float* out = (float*)d_out;

    __half *x0h, *h1, *h2;
    int *u_ptr, *i_ptr, *i_work, *cnt, *bsums;
    int2 *tedge;
    cudaGetSymbolAddress((void**)&x0h, g_x0);
    cudaGetSymbolAddress((void**)&h1, g_h1);
    cudaGetSymbolAddress((void**)&h2, g_h2);
    cudaGetSymbolAddress((void**)&tedge, g_tedge);
    cudaGetSymbolAddress((void**)&u_ptr, g_u_ptr);
    cudaGetSymbolAddress((void**)&i_ptr, g_i_ptr);
    cudaGetSymbolAddress((void**)&i_work, g_i_work);
    cudaGetSymbolAddress((void**)&cnt, g_cnt);
    cudaGetSymbolAddress((void**)&bsums, g_bsums);

    const int TB = 256;
    const int n_u4 = n_total * 8;
    const int n_user_u4 = n_users * 8;
    const int n_cnt = n_items + 1;

    // 0. zero item counters (tiny)
    zero_cnt_kernel<<<(n_cnt + TB - 1) / TB, TB>>>(cnt, n_cnt);

    // 1. fused prep: fp16 convert + item-degree count + u_ptr search
    int prep_threads = n_u4 + P + n_users + 1;
    fused_prep_kernel<<<(prep_threads + TB - 1) / TB, TB>>>(
        (const float4*)user_emb, (const float4*)item_emb, (uint4*)x0h,
        row, col, cnt, u_ptr, n_user_u4, n_u4, P, n_users);

    // 2-4. exclusive scan -> i_ptr
    int n_scan = n_cnt;
    int nb = (n_scan + SCAN_BLK - 1) / SCAN_BLK;
    scan1_kernel<<<nb, SCAN_BLK>>>(cnt, i_ptr, bsums, n_scan);
    scan2_kernel<<<1, 512>>>(bsums, nb);
    scan3_kernel<<<(n_scan + TB - 1) / TB, TB>>>(i_ptr, i_work, bsums, n_scan);

    // 5. scatter transpose (item CSC)
    scatter_kernel<<<(P + TB - 1) / TB, TB>>>(row, col, vals, P, i_work, tedge, n_users);

    // 6-8. three SpMM layers (R8 structure: natural order, 8 lanes/row)
    int spmm_blocks = (n_total * 8 + TB - 1) / TB;
    spmm_kernel<<<spmm_blocks, TB>>>((const uint4*)x0h, (uint4*)h1,
                                     col, vals, tedge, u_ptr, i_ptr, n_users, n_total);
    spmm_kernel<<<spmm_blocks, TB>>>((const uint4*)h1, (uint4*)h2,
                                     col, vals, tedge, u_ptr, i_ptr, n_users, n_total);
    spmm_final_kernel<<<spmm_blocks, TB>>>((const uint4*)h2, (const uint4*)x0h,
                                           (const uint4*)h1, (float4*)out,
                                           col, vals, tedge, u_ptr, i_ptr, n_users, n_total);
}

// round 14
// speedup vs baseline: 1.3195x; 1.0108x over previous
#include <cuda_runtime.h>
#include <cuda_fp16.h>

#define D 64
#define NU_MAX 100001
#define NI_MAX 200001
#define NMAX (NU_MAX + NI_MAX)
#define PMAX 3200000
#define SCAN_BLK 1024

__device__ __forceinline__ __half2 u2h2(unsigned u) {
    __half2 h; *reinterpret_cast<unsigned*>(&h) = u; return h;
}
__device__ __forceinline__ unsigned h22u(__half2 h) {
    return *reinterpret_cast<unsigned*>(&h);
}

// Scratch (.bss, no allocation). fp16 feature rows: 64 halves = 128B.
__device__ __half g_x0[(size_t)NMAX * D];
__device__ __half g_h1[(size_t)NMAX * D];
__device__ __half g_h2[(size_t)NMAX * D];
__device__ int2   g_tedge[PMAX];          // item CSC packed {col(user), val_bits}
__device__ int    g_u_ptr[NU_MAX + 2];
__device__ int    g_i_ptr[NI_MAX + 2];
__device__ int    g_i_work[NI_MAX + 2];
__device__ int    g_cnt[NI_MAX + 2];
__device__ int    g_bsums[512];

// ---------------------------------------------------------------------------
// zero item-degree counters
// ---------------------------------------------------------------------------
__global__ void zero_cnt_kernel(int* __restrict__ cnt, int n_cnt) {
    int i = blockIdx.x * blockDim.x + threadIdx.x;
    if (i < n_cnt) cnt[i] = 0;
}

// ---------------------------------------------------------------------------
// fused prep: fp16 convert | item-degree count | u_ptr binary search
// ---------------------------------------------------------------------------
__global__ void fused_prep_kernel(const float4* __restrict__ ue,
                                  const float4* __restrict__ ie,
                                  uint4* __restrict__ x0,
                                  const int* __restrict__ row,
                                  const int* __restrict__ col,
                                  int* __restrict__ cnt,
                                  int* __restrict__ uptr,
                                  int n_user_u4, int n_u4, int P, int n_users) {
    int t = blockIdx.x * blockDim.x + threadIdx.x;
    if (t < n_u4) {
        const float4* src = (t < n_user_u4) ? (ue + (size_t)t * 2)
                                            : (ie + (size_t)(t - n_user_u4) * 2);
        float4 f0 = src[0];
        float4 f1 = src[1];
        uint4 o;
        o.x = h22u(__floats2half2_rn(f0.x, f0.y));
        o.y = h22u(__floats2half2_rn(f0.z, f0.w));
        o.z = h22u(__floats2half2_rn(f1.x, f1.y));
        o.w = h22u(__floats2half2_rn(f1.z, f1.w));
        x0[t] = o;
    } else if (t < n_u4 + P) {
        int e = t - n_u4;
        atomicAdd(&cnt[col[e] - n_users], 1);
    } else {
        int r = t - n_u4 - P;
        if (r > n_users) return;
        int lo = 0, hi = P;
        while (lo < hi) {
            int mid = (lo + hi) >> 1;
            if (row[mid] < r) lo = mid + 1; else hi = mid;
        }
        uptr[r] = lo;
    }
}

// ---------------------------------------------------------------------------
// exclusive scan of cnt[0:n] -> i_ptr
// ---------------------------------------------------------------------------
__global__ void scan1_kernel(const int* __restrict__ cnt, int* __restrict__ ptr,
                             int* __restrict__ bsums, int n) {
    __shared__ int sh[SCAN_BLK];
    int i = blockIdx.x * SCAN_BLK + threadIdx.x;
    int v = (i < n) ? cnt[i] : 0;
    sh[threadIdx.x] = v;
    __syncthreads();
    for (int off = 1; off < SCAN_BLK; off <<= 1) {
        int t = 0;
        if ((int)threadIdx.x >= off) t = sh[threadIdx.x - off];
        __syncthreads();
        sh[threadIdx.x] += t;
        __syncthreads();
    }
    if (i < n) ptr[i] = sh[threadIdx.x] - v;
    if (threadIdx.x == SCAN_BLK - 1) bsums[blockIdx.x] = sh[SCAN_BLK - 1];
}

__global__ void scan2_kernel(int* __restrict__ bsums, int nb) {
    __shared__ int sh[512];
    int v = ((int)threadIdx.x < nb) ? bsums[threadIdx.x] : 0;
    sh[threadIdx.x] = v;
    __syncthreads();
    for (int off = 1; off < 512; off <<= 1) {
        int t = 0;
        if ((int)threadIdx.x >= off) t = sh[threadIdx.x - off];
        __syncthreads();
        sh[threadIdx.x] += t;
        __syncthreads();
    }
    if ((int)threadIdx.x < nb) bsums[threadIdx.x] = sh[threadIdx.x] - v;
}

__global__ void scan3_kernel(int* __restrict__ ptr, int* __restrict__ work,
                             const int* __restrict__ bsums, int n) {
    int i = blockIdx.x * blockDim.x + threadIdx.x;
    if (i >= n) return;
    int p = ptr[i] + bsums[i >> 10];
    ptr[i] = p;
    work[i] = p;
}

// ---------------------------------------------------------------------------
// scatter transpose (item CSC), single 8B store
// ---------------------------------------------------------------------------
__global__ void scatter_kernel(const int* __restrict__ row,
                               const int* __restrict__ col,
                               const float* __restrict__ vals, int P,
                               int* __restrict__ iwork,
                               int2* __restrict__ tedge, int n_users) {
    int e = blockIdx.x * blockDim.x + threadIdx.x;
    if (e >= P) return;
    int it = col[e] - n_users;
    int pos = atomicAdd(&iwork[it], 1);
    tedge[pos] = make_int2(row[e], __float_as_int(vals[e]));
}

// ---------------------------------------------------------------------------
// SpMM, 8 lanes per row, fp16 gather via LDG.128. Row range [base, base+count).
// User rows read col[]/vals[] directly; item rows read packed int2 CSC.
// ---------------------------------------------------------------------------
#define FMA_ROW(c_, v_)  {                                                   \
    uint4 u_ = x[(size_t)(c_) * 8 + lane];                                   \
    float2 f0_ = __half22float2(u2h2(u_.x));                                 \
    float2 f1_ = __half22float2(u2h2(u_.y));                                 \
    float2 f2_ = __half22float2(u2h2(u_.z));                                 \
    float2 f3_ = __half22float2(u2h2(u_.w));                                 \
    a0 = fmaf(v_, f0_.x, a0); a1 = fmaf(v_, f0_.y, a1);                      \
    a2 = fmaf(v_, f1_.x, a2); a3 = fmaf(v_, f1_.y, a3);                      \
    a4 = fmaf(v_, f2_.x, a4); a5 = fmaf(v_, f2_.y, a5);                      \
    a6 = fmaf(v_, f3_.x, a6); a7 = fmaf(v_, f3_.y, a7); }

__device__ __forceinline__ void accum_user(const uint4* __restrict__ x,
                                           const int* __restrict__ col,
                                           const float* __restrict__ val,
                                           int s, int e, int lane,
                                           float& a0, float& a1, float& a2, float& a3,
                                           float& a4, float& a5, float& a6, float& a7) {
    int ei = s;
    while (ei < e && (ei & 3)) {               // align to 16B
        FMA_ROW(col[ei], val[ei])
        ei++;
    }
    for (; ei + 8 <= e; ei += 8) {
        int4   c0 = *reinterpret_cast<const int4*>(col + ei);
        int4   c1 = *reinterpret_cast<const int4*>(col + ei + 4);
        float4 v0 = *reinterpret_cast<const float4*>(val + ei);
        float4 v1 = *reinterpret_cast<const float4*>(val + ei + 4);
        FMA_ROW(c0.x, v0.x) FMA_ROW(c0.y, v0.y)
        FMA_ROW(c0.z, v0.z) FMA_ROW(c0.w, v0.w)
        FMA_ROW(c1.x, v1.x) FMA_ROW(c1.y, v1.y)
        FMA_ROW(c1.z, v1.z) FMA_ROW(c1.w, v1.w)
    }
    for (; ei < e; ei++) {
        FMA_ROW(col[ei], val[ei])
    }
}

__device__ __forceinline__ void accum_item(const uint4* __restrict__ x,
                                           const int2* __restrict__ tedge,
                                           int s, int e, int lane,
                                           float& a0, float& a1, float& a2, float& a3,
                                           float& a4, float& a5, float& a6, float& a7) {
    int ei = s;
    if (ei < e && (ei & 1)) {
        int2 p = tedge[ei];
        FMA_ROW(p.x, __int_as_float(p.y))
        ei++;
    }
    for (; ei + 8 <= e; ei += 8) {
        int4 p0 = *reinterpret_cast<const int4*>(tedge + ei);
        int4 p1 = *reinterpret_cast<const int4*>(tedge + ei + 2);
        int4 p2 = *reinterpret_cast<const int4*>(tedge + ei + 4);
        int4 p3 = *reinterpret_cast<const int4*>(tedge + ei + 6);
        FMA_ROW(p0.x, __int_as_float(p0.y)) FMA_ROW(p0.z, __int_as_float(p0.w))
        FMA_ROW(p1.x, __int_as_float(p1.y)) FMA_ROW(p1.z, __int_as_float(p1.w))
        FMA_ROW(p2.x, __int_as_float(p2.y)) FMA_ROW(p2.z, __int_as_float(p2.w))
        FMA_ROW(p3.x, __int_as_float(p3.y)) FMA_ROW(p3.z, __int_as_float(p3.w))
    }
    for (; ei < e; ei++) {
        int2 p = tedge[ei];
        FMA_ROW(p.x, __int_as_float(p.y))
    }
}

__global__ void spmm_kernel(const uint4* __restrict__ x,
                            uint4* __restrict__ y,
                            const int* __restrict__ col,
                            const float* __restrict__ val,
                            const int2* __restrict__ tedge,
                            const int* __restrict__ uptr,
                            const int* __restrict__ iptr,
                            int n_users, int base, int count) {
    int g = base + ((blockIdx.x * blockDim.x + threadIdx.x) >> 3);
    int lane = threadIdx.x & 7;
    if (g >= base + count) return;

    float a0 = 0.f, a1 = 0.f, a2 = 0.f, a3 = 0.f,
          a4 = 0.f, a5 = 0.f, a6 = 0.f, a7 = 0.f;
    if (g < n_users) {
        int s = uptr[g], e = uptr[g + 1];
        accum_user(x, col, val, s, e, lane, a0, a1, a2, a3, a4, a5, a6, a7);
    } else {
        int ii = g - n_users;
        int s = iptr[ii], e = iptr[ii + 1];
        accum_item(x, tedge, s, e, lane, a0, a1, a2, a3, a4, a5, a6, a7);
    }

    uint4 o;
    o.x = h22u(__floats2half2_rn(a0, a1));
    o.y = h22u(__floats2half2_rn(a2, a3));
    o.z = h22u(__floats2half2_rn(a4, a5));
    o.w = h22u(__floats2half2_rn(a6, a7));
    y[(size_t)g * 8 + lane] = o;
}

// last layer + epilogue: out = (x0 + h1 + h2 + acc) * 0.25
__global__ void spmm_final_kernel(const uint4* __restrict__ x,   // h2
                                  const uint4* __restrict__ x0,
                                  const uint4* __restrict__ h1,
                                  float4* __restrict__ out,
                                  const int* __restrict__ col,
                                  const float* __restrict__ val,
                                  const int2* __restrict__ tedge,
                                  const int* __restrict__ uptr,
                                  const int* __restrict__ iptr,
                                  int n_users, int n_total) {
    int g = (blockIdx.x * blockDim.x + threadIdx.x) >> 3;
    int lane = threadIdx.x & 7;
    if (g >= n_total) return;

    float a0 = 0.f, a1 = 0.f, a2 = 0.f, a3 = 0.f,
          a4 = 0.f, a5 = 0.f, a6 = 0.f, a7 = 0.f;
    if (g < n_users) {
        int s = uptr[g], e = uptr[g + 1];
        accum_user(x, col, val, s, e, lane, a0, a1, a2, a3, a4, a5, a6, a7);
    } else {
        int ii = g - n_users;
        int s = iptr[ii], e = iptr[ii + 1];
        accum_item(x, tedge, s, e, lane, a0, a1, a2, a3, a4, a5, a6, a7);
    }

    size_t hoff = (size_t)g * 8 + lane;
    uint4 u0 = x0[hoff];
    uint4 u1 = h1[hoff];
    uint4 u2 = x[hoff];
    float2 z0 = __half22float2(u2h2(u0.x));
    float2 z1 = __half22float2(u2h2(u0.y));
    float2 z2 = __half22float2(u2h2(u0.z));
    float2 z3 = __half22float2(u2h2(u0.w));
    float2 b0 = __half22float2(u2h2(u1.x));
    float2 b1 = __half22float2(u2h2(u1.y));
    float2 b2 = __half22float2(u2h2(u1.z));
    float2 b3 = __half22float2(u2h2(u1.w));
    float2 c0 = __half22float2(u2h2(u2.x));
    float2 c1 = __half22float2(u2h2(u2.y));
    float2 c2 = __half22float2(u2h2(u2.z));
    float2 c3 = __half22float2(u2h2(u2.w));

    float4 r0v, r1v;
    r0v.x = (z0.x + b0.x + c0.x + a0) * 0.25f;
    r0v.y = (z0.y + b0.y + c0.y + a1) * 0.25f;
    r0v.z = (z1.x + b1.x + c1.x + a2) * 0.25f;
    r0v.w = (z1.y + b1.y + c1.y + a3) * 0.25f;
    r1v.x = (z2.x + b2.x + c2.x + a4) * 0.25f;
    r1v.y = (z2.y + b2.y + c2.y + a5) * 0.25f;
    r1v.z = (z3.x + b3.x + c3.x + a6) * 0.25f;
    r1v.w = (z3.y + b3.y + c3.y + a7) * 0.25f;
    size_t foff = (size_t)g * 16 + lane * 2;
    out[foff] = r0v;
    out[foff + 1] = r1v;
}

extern "C" void kernel_launch(void* const* d_in, const int* in_sizes, int n_in,
                              void* d_out, int out_size) {
    const float* user_emb = (const float*)d_in[0];
    const float* item_emb = (const float*)d_in[1];
    const int*   row      = (const int*)d_in[2];
    const int*   col      = (const int*)d_in[3];
    const float* vals     = (const float*)d_in[4];

    const int n_users = in_sizes[0] / D;
    const int n_items = in_sizes[1] / D;
    const int n_total = n_users + n_items;
    const int E       = in_sizes[2];
    const int P       = E / 2;

    float* out = (float*)d_out;

    __half *x0h, *h1, *h2;
    int *u_ptr, *i_ptr, *i_work, *cnt, *bsums;
    int2 *tedge;
    cudaGetSymbolAddress((void**)&x0h, g_x0);
    cudaGetSymbolAddress((void**)&h1, g_h1);
    cudaGetSymbolAddress((void**)&h2, g_h2);
    cudaGetSymbolAddress((void**)&tedge, g_tedge);
    cudaGetSymbolAddress((void**)&u_ptr, g_u_ptr);
    cudaGetSymbolAddress((void**)&i_ptr, g_i_ptr);
    cudaGetSymbolAddress((void**)&i_work, g_i_work);
    cudaGetSymbolAddress((void**)&cnt, g_cnt);
    cudaGetSymbolAddress((void**)&bsums, g_bsums);

    // Side stream + events: created once, reused (graph shape identical per call)
    static cudaStream_t s1 = nullptr;
    static cudaEvent_t evA = nullptr, evB = nullptr;
    if (!s1) {
        cudaStreamCreateWithFlags(&s1, cudaStreamNonBlocking);
        cudaEventCreateWithFlags(&evA, cudaEventDisableTiming);
        cudaEventCreateWithFlags(&evB, cudaEventDisableTiming);
    }

    const int TB = 256;
    const int n_u4 = n_total * 8;
    const int n_user_u4 = n_users * 8;
    const int n_cnt = n_items + 1;

    // s0: zero counters, fused prep
    zero_cnt_kernel<<<(n_cnt + TB - 1) / TB, TB>>>(cnt, n_cnt);
    int prep_threads = n_u4 + P + n_users + 1;
    fused_prep_kernel<<<(prep_threads + TB - 1) / TB, TB>>>(
        (const float4*)user_emb, (const float4*)item_emb, (uint4*)x0h,
        row, col, cnt, u_ptr, n_user_u4, n_u4, P, n_users);

    cudaEventRecord(evA, 0);

    // s0: layer-0 USER half (needs only x0h + u_ptr) — overlaps with s1 chain
    int user_blocks = (n_users * 8 + TB - 1) / TB;
    spmm_kernel<<<user_blocks, TB>>>((const uint4*)x0h, (uint4*)h1,
                                     col, vals, tedge, u_ptr, i_ptr,
                                     n_users, 0, n_users);

    // s1: scan chain + scatter + layer-0 ITEM half
    cudaStreamWaitEvent(s1, evA, 0);
    int n_scan = n_cnt;
    int nb = (n_scan + SCAN_BLK - 1) / SCAN_BLK;
    scan1_kernel<<<nb, SCAN_BLK, 0, s1>>>(cnt, i_ptr, bsums, n_scan);
    scan2_kernel<<<1, 512, 0, s1>>>(bsums, nb);
    scan3_kernel<<<(n_scan + TB - 1) / TB, TB, 0, s1>>>(i_ptr, i_work, bsums, n_scan);
    scatter_kernel<<<(P + TB - 1) / TB, TB, 0, s1>>>(row, col, vals, P, i_work,
                                                     tedge, n_users);
    int item_blocks = (n_items * 8 + TB - 1) / TB;
    spmm_kernel<<<item_blocks, TB, 0, s1>>>((const uint4*)x0h, (uint4*)h1,
                                            col, vals, tedge, u_ptr, i_ptr,
                                            n_users, n_users, n_items);
    cudaEventRecord(evB, s1);

    // s0: join, then layers 1-2 (full graph)
    cudaStreamWaitEvent(0, evB, 0);
    int spmm_blocks = (n_total * 8 + TB - 1) / TB;
    spmm_kernel<<<spmm_blocks, TB>>>((const uint4*)h1, (uint4*)h2,
                                     col, vals, tedge, u_ptr, i_ptr,
                                     n_users, 0, n_total);
    spmm_final_kernel<<<spmm_blocks, TB>>>((const uint4*)h2, (const uint4*)x0h,
                                           (const uint4*)h1, (float4*)out,
                                           col, vals, tedge, u_ptr, i_ptr,
                                           n_users, n_total);
}

// round 15
// speedup vs baseline: 1.3806x; 1.0463x over previous
#include <cuda_runtime.h>
#include <cuda_fp16.h>

#define D 64
#define NU_MAX 100001
#define NI_MAX 200001
#define NMAX (NU_MAX + NI_MAX)
#define PMAX 3200000
#define SCAN_BLK 1024

__device__ __forceinline__ __half2 u2h2(unsigned u) {
    __half2 h; *reinterpret_cast<unsigned*>(&h) = u; return h;
}
__device__ __forceinline__ unsigned h22u(__half2 h) {
    return *reinterpret_cast<unsigned*>(&h);
}

// Scratch (.bss, no allocation). fp16 feature rows: 64 halves = 128B.
__device__ __half g_x0[(size_t)NMAX * D];
__device__ __half g_h1[(size_t)NMAX * D];
__device__ __half g_h2[(size_t)NMAX * D];
__device__ int2   g_tedge[PMAX];          // item CSC packed {col(user), val_bits}
__device__ int    g_u_ptr[NU_MAX + 2];
__device__ int    g_i_ptr[NI_MAX + 2];
__device__ int    g_i_work[NI_MAX + 2];
__device__ int    g_cnt[NI_MAX + 2];
__device__ int    g_bsums[512];

// ---------------------------------------------------------------------------
// s0 prep: fp16 convert + u_ptr binary search (no dependence on cnt)
// ---------------------------------------------------------------------------
__global__ void convert_uptr_kernel(const float4* __restrict__ ue,
                                    const float4* __restrict__ ie,
                                    uint4* __restrict__ x0,
                                    const int* __restrict__ row,
                                    int* __restrict__ uptr,
                                    int n_user_u4, int n_u4, int P, int n_users) {
    int t = blockIdx.x * blockDim.x + threadIdx.x;
    if (t < n_u4) {
        const float4* src = (t < n_user_u4) ? (ue + (size_t)t * 2)
                                            : (ie + (size_t)(t - n_user_u4) * 2);
        float4 f0 = src[0];
        float4 f1 = src[1];
        uint4 o;
        o.x = h22u(__floats2half2_rn(f0.x, f0.y));
        o.y = h22u(__floats2half2_rn(f0.z, f0.w));
        o.z = h22u(__floats2half2_rn(f1.x, f1.y));
        o.w = h22u(__floats2half2_rn(f1.z, f1.w));
        x0[t] = o;
    } else {
        int r = t - n_u4;
        if (r > n_users) return;
        int lo = 0, hi = P;
        while (lo < hi) {
            int mid = (lo + hi) >> 1;
            if (row[mid] < r) lo = mid + 1; else hi = mid;
        }
        uptr[r] = lo;
    }
}

// ---------------------------------------------------------------------------
// s1 prep: item degree count (needs only col input + zeroed cnt)
// ---------------------------------------------------------------------------
__global__ void count_kernel(const int* __restrict__ col, int P,
                             int* __restrict__ cnt, int n_users) {
    int e = blockIdx.x * blockDim.x + threadIdx.x;
    if (e >= P) return;
    atomicAdd(&cnt[col[e] - n_users], 1);
}

// ---------------------------------------------------------------------------
// exclusive scan of cnt[0:n] -> i_ptr
// ---------------------------------------------------------------------------
__global__ void scan1_kernel(const int* __restrict__ cnt, int* __restrict__ ptr,
                             int* __restrict__ bsums, int n) {
    __shared__ int sh[SCAN_BLK];
    int i = blockIdx.x * SCAN_BLK + threadIdx.x;
    int v = (i < n) ? cnt[i] : 0;
    sh[threadIdx.x] = v;
    __syncthreads();
    for (int off = 1; off < SCAN_BLK; off <<= 1) {
        int t = 0;
        if ((int)threadIdx.x >= off) t = sh[threadIdx.x - off];
        __syncthreads();
        sh[threadIdx.x] += t;
        __syncthreads();
    }
    if (i < n) ptr[i] = sh[threadIdx.x] - v;
    if (threadIdx.x == SCAN_BLK - 1) bsums[blockIdx.x] = sh[SCAN_BLK - 1];
}

__global__ void scan2_kernel(int* __restrict__ bsums, int nb) {
    __shared__ int sh[512];
    int v = ((int)threadIdx.x < nb) ? bsums[threadIdx.x] : 0;
    sh[threadIdx.x] = v;
    __syncthreads();
    for (int off = 1; off < 512; off <<= 1) {
        int t = 0;
        if ((int)threadIdx.x >= off) t = sh[threadIdx.x - off];
        __syncthreads();
        sh[threadIdx.x] += t;
        __syncthreads();
    }
    if ((int)threadIdx.x < nb) bsums[threadIdx.x] = sh[threadIdx.x] - v;
}

__global__ void scan3_kernel(int* __restrict__ ptr, int* __restrict__ work,
                             const int* __restrict__ bsums, int n) {
    int i = blockIdx.x * blockDim.x + threadIdx.x;
    if (i >= n) return;
    int p = ptr[i] + bsums[i >> 10];
    ptr[i] = p;
    work[i] = p;
}

// ---------------------------------------------------------------------------
// scatter transpose (item CSC), single 8B store
// ---------------------------------------------------------------------------
__global__ void scatter_kernel(const int* __restrict__ row,
                               const int* __restrict__ col,
                               const float* __restrict__ vals, int P,
                               int* __restrict__ iwork,
                               int2* __restrict__ tedge, int n_users) {
    int e = blockIdx.x * blockDim.x + threadIdx.x;
    if (e >= P) return;
    int it = col[e] - n_users;
    int pos = atomicAdd(&iwork[it], 1);
    tedge[pos] = make_int2(row[e], __float_as_int(vals[e]));
}

// ---------------------------------------------------------------------------
// SpMM, 8 lanes per row, fp16 gather via LDG.128. Row range [base, base+count).
// ---------------------------------------------------------------------------
#define FMA_ROW(c_, v_)  {                                                   \
    uint4 u_ = x[(size_t)(c_) * 8 + lane];                                   \
    float2 f0_ = __half22float2(u2h2(u_.x));                                 \
    float2 f1_ = __half22float2(u2h2(u_.y));                                 \
    float2 f2_ = __half22float2(u2h2(u_.z));                                 \
    float2 f3_ = __half22float2(u2h2(u_.w));                                 \
    a0 = fmaf(v_, f0_.x, a0); a1 = fmaf(v_, f0_.y, a1);                      \
    a2 = fmaf(v_, f1_.x, a2); a3 = fmaf(v_, f1_.y, a3);                      \
    a4 = fmaf(v_, f2_.x, a4); a5 = fmaf(v_, f2_.y, a5);                      \
    a6 = fmaf(v_, f3_.x, a6); a7 = fmaf(v_, f3_.y, a7); }

__device__ __forceinline__ void accum_user(const uint4* __restrict__ x,
                                           const int* __restrict__ col,
                                           const float* __restrict__ val,
                                           int s, int e, int lane,
                                           float& a0, float& a1, float& a2, float& a3,
                                           float& a4, float& a5, float& a6, float& a7) {
    int ei = s;
    while (ei < e && (ei & 3)) {               // align to 16B
        FMA_ROW(col[ei], val[ei])
        ei++;
    }
    for (; ei + 8 <= e; ei += 8) {
        int4   c0 = *reinterpret_cast<const int4*>(col + ei);
        int4   c1 = *reinterpret_cast<const int4*>(col + ei + 4);
        float4 v0 = *reinterpret_cast<const float4*>(val + ei);
        float4 v1 = *reinterpret_cast<const float4*>(val + ei + 4);
        FMA_ROW(c0.x, v0.x) FMA_ROW(c0.y, v0.y)
        FMA_ROW(c0.z, v0.z) FMA_ROW(c0.w, v0.w)
        FMA_ROW(c1.x, v1.x) FMA_ROW(c1.y, v1.y)
        FMA_ROW(c1.z, v1.z) FMA_ROW(c1.w, v1.w)
    }
    for (; ei < e; ei++) {
        FMA_ROW(col[ei], val[ei])
    }
}

__device__ __forceinline__ void accum_item(const uint4* __restrict__ x,
                                           const int2* __restrict__ tedge,
                                           int s, int e, int lane,
                                           float& a0, float& a1, float& a2, float& a3,
                                           float& a4, float& a5, float& a6, float& a7) {
    int ei = s;
    if (ei < e && (ei & 1)) {
        int2 p = tedge[ei];
        FMA_ROW(p.x, __int_as_float(p.y))
        ei++;
    }
    for (; ei + 8 <= e; ei += 8) {
        int4 p0 = *reinterpret_cast<const int4*>(tedge + ei);
        int4 p1 = *reinterpret_cast<const int4*>(tedge + ei + 2);
        int4 p2 = *reinterpret_cast<const int4*>(tedge + ei + 4);
        int4 p3 = *reinterpret_cast<const int4*>(tedge + ei + 6);
        FMA_ROW(p0.x, __int_as_float(p0.y)) FMA_ROW(p0.z, __int_as_float(p0.w))
        FMA_ROW(p1.x, __int_as_float(p1.y)) FMA_ROW(p1.z, __int_as_float(p1.w))
        FMA_ROW(p2.x, __int_as_float(p2.y)) FMA_ROW(p2.z, __int_as_float(p2.w))
        FMA_ROW(p3.x, __int_as_float(p3.y)) FMA_ROW(p3.z, __int_as_float(p3.w))
    }
    for (; ei < e; ei++) {
        int2 p = tedge[ei];
        FMA_ROW(p.x, __int_as_float(p.y))
    }
}

__global__ void __launch_bounds__(256, 5)
spmm_kernel(const uint4* __restrict__ x,
            uint4* __restrict__ y,
            const int* __restrict__ col,
            const float* __restrict__ val,
            const int2* __restrict__ tedge,
            const int* __restrict__ uptr,
            const int* __restrict__ iptr,
            int n_users, int base, int count) {
    int g = base + ((blockIdx.x * blockDim.x + threadIdx.x) >> 3);
    int lane = threadIdx.x & 7;
    if (g >= base + count) return;

    float a0 = 0.f, a1 = 0.f, a2 = 0.f, a3 = 0.f,
          a4 = 0.f, a5 = 0.f, a6 = 0.f, a7 = 0.f;
    if (g < n_users) {
        int s = uptr[g], e = uptr[g + 1];
        accum_user(x, col, val, s, e, lane, a0, a1, a2, a3, a4, a5, a6, a7);
    } else {
        int ii = g - n_users;
        int s = iptr[ii], e = iptr[ii + 1];
        accum_item(x, tedge, s, e, lane, a0, a1, a2, a3, a4, a5, a6, a7);
    }

    uint4 o;
    o.x = h22u(__floats2half2_rn(a0, a1));
    o.y = h22u(__floats2half2_rn(a2, a3));
    o.z = h22u(__floats2half2_rn(a4, a5));
    o.w = h22u(__floats2half2_rn(a6, a7));
    y[(size_t)g * 8 + lane] = o;
}

// last layer + epilogue: out = (x0 + h1 + h2 + acc) * 0.25
__global__ void __launch_bounds__(256, 5)
spmm_final_kernel(const uint4* __restrict__ x,   // h2
                  const uint4* __restrict__ x0,
                  const uint4* __restrict__ h1,
                  float4* __restrict__ out,
                  const int* __restrict__ col,
                  const float* __restrict__ val,
                  const int2* __restrict__ tedge,
                  const int* __restrict__ uptr,
                  const int* __restrict__ iptr,
                  int n_users, int n_total) {
    int g = (blockIdx.x * blockDim.x + threadIdx.x) >> 3;
    int lane = threadIdx.x & 7;
    if (g >= n_total) return;

    float a0 = 0.f, a1 = 0.f, a2 = 0.f, a3 = 0.f,
          a4 = 0.f, a5 = 0.f, a6 = 0.f, a7 = 0.f;
    if (g < n_users) {
        int s = uptr[g], e = uptr[g + 1];
        accum_user(x, col, val, s, e, lane, a0, a1, a2, a3, a4, a5, a6, a7);
    } else {
        int ii = g - n_users;
        int s = iptr[ii], e = iptr[ii + 1];
        accum_item(x, tedge, s, e, lane, a0, a1, a2, a3, a4, a5, a6, a7);
    }

    size_t hoff = (size_t)g * 8 + lane;
    uint4 u0 = x0[hoff];
    uint4 u1 = h1[hoff];
    uint4 u2 = x[hoff];
    float2 z0 = __half22float2(u2h2(u0.x));
    float2 z1 = __half22float2(u2h2(u0.y));
    float2 z2 = __half22float2(u2h2(u0.z));
    float2 z3 = __half22float2(u2h2(u0.w));
    float2 b0 = __half22float2(u2h2(u1.x));
    float2 b1 = __half22float2(u2h2(u1.y));
    float2 b2 = __half22float2(u2h2(u1.z));
    float2 b3 = __half22float2(u2h2(u1.w));
    float2 c0 = __half22float2(u2h2(u2.x));
    float2 c1 = __half22float2(u2h2(u2.y));
    float2 c2 = __half22float2(u2h2(u2.z));
    float2 c3 = __half22float2(u2h2(u2.w));

    float4 r0v, r1v;
    r0v.x = (z0.x + b0.x + c0.x + a0) * 0.25f;
    r0v.y = (z0.y + b0.y + c0.y + a1) * 0.25f;
    r0v.z = (z1.x + b1.x + c1.x + a2) * 0.25f;
    r0v.w = (z1.y + b1.y + c1.y + a3) * 0.25f;
    r1v.x = (z2.x + b2.x + c2.x + a4) * 0.25f;
    r1v.y = (z2.y + b2.y + c2.y + a5) * 0.25f;
    r1v.z = (z3.x + b3.x + c3.x + a6) * 0.25f;
    r1v.w = (z3.y + b3.y + c3.y + a7) * 0.25f;
    size_t foff = (size_t)g * 16 + lane * 2;
    out[foff] = r0v;
    out[foff + 1] = r1v;
}

extern "C" void kernel_launch(void* const* d_in, const int* in_sizes, int n_in,
                              void* d_out, int out_size) {
    const float* user_emb = (const float*)d_in[0];
    const float* item_emb = (const float*)d_in[1];
    const int*   row      = (const int*)d_in[2];
    const int*   col      = (const int*)d_in[3];
    const float* vals     = (const float*)d_in[4];

    const int n_users = in_sizes[0] / D;
    const int n_items = in_sizes[1] / D;
    const int n_total = n_users + n_items;
    const int E       = in_sizes[2];
    const int P       = E / 2;

    float* out = (float*)d_out;

    __half *x0h, *h1, *h2;
    int *u_ptr, *i_ptr, *i_work, *cnt, *bsums;
    int2 *tedge;
    cudaGetSymbolAddress((void**)&x0h, g_x0);
    cudaGetSymbolAddress((void**)&h1, g_h1);
    cudaGetSymbolAddress((void**)&h2, g_h2);
    cudaGetSymbolAddress((void**)&tedge, g_tedge);
    cudaGetSymbolAddress((void**)&u_ptr, g_u_ptr);
    cudaGetSymbolAddress((void**)&i_ptr, g_i_ptr);
    cudaGetSymbolAddress((void**)&i_work, g_i_work);
    cudaGetSymbolAddress((void**)&cnt, g_cnt);
    cudaGetSymbolAddress((void**)&bsums, g_bsums);

    // Side stream + events: created once, reused (graph shape identical per call)
    static cudaStream_t s1 = nullptr;
    static cudaEvent_t evRoot = nullptr, evA = nullptr, evB = nullptr;
    if (!s1) {
        cudaStreamCreateWithFlags(&s1, cudaStreamNonBlocking);
        cudaEventCreateWithFlags(&evRoot, cudaEventDisableTiming);
        cudaEventCreateWithFlags(&evA, cudaEventDisableTiming);
        cudaEventCreateWithFlags(&evB, cudaEventDisableTiming);
    }

    const int TB = 256;
    const int n_u4 = n_total * 8;
    const int n_user_u4 = n_users * 8;
    const int n_cnt = n_items + 1;

    // fork s1 off the capture stream
    cudaEventRecord(evRoot, 0);
    cudaStreamWaitEvent(s1, evRoot, 0);

    // s1: item CSC chain (independent of convert): zero -> count -> scan -> scatter
    cudaMemsetAsync(cnt, 0, n_cnt * sizeof(int), s1);
    count_kernel<<<(P + TB - 1) / TB, TB, 0, s1>>>(col, P, cnt, n_users);
    int n_scan = n_cnt;
    int nb = (n_scan + SCAN_BLK - 1) / SCAN_BLK;
    scan1_kernel<<<nb, SCAN_BLK, 0, s1>>>(cnt, i_ptr, bsums, n_scan);
    scan2_kernel<<<1, 512, 0, s1>>>(bsums, nb);
    scan3_kernel<<<(n_scan + TB - 1) / TB, TB, 0, s1>>>(i_ptr, i_work, bsums, n_scan);
    scatter_kernel<<<(P + TB - 1) / TB, TB, 0, s1>>>(row, col, vals, P, i_work,
                                                     tedge, n_users);

    // s0: fp16 convert + u_ptr, then layer-0 USER half
    int cu_threads = n_u4 + n_users + 1;
    convert_uptr_kernel<<<(cu_threads + TB - 1) / TB, TB>>>(
        (const float4*)user_emb, (const float4*)item_emb, (uint4*)x0h,
        row, u_ptr, n_user_u4, n_u4, P, n_users);
    cudaEventRecord(evA, 0);
    int user_blocks = (n_users * 8 + TB - 1) / TB;
    spmm_kernel<<<user_blocks, TB>>>((const uint4*)x0h, (uint4*)h1,
                                     col, vals, tedge, u_ptr, i_ptr,
                                     n_users, 0, n_users);

    // s1: layer-0 ITEM half (needs x0h from s0 + tedge/i_ptr from s1)
    cudaStreamWaitEvent(s1, evA, 0);
    int item_blocks = (n_items * 8 + TB - 1) / TB;
    spmm_kernel<<<item_blocks, TB, 0, s1>>>((const uint4*)x0h, (uint4*)h1,
                                            col, vals, tedge, u_ptr, i_ptr,
                                            n_users, n_users, n_items);
    cudaEventRecord(evB, s1);

    // s0: join, then layers 1-2 (full graph)
    cudaStreamWaitEvent(0, evB, 0);
    int spmm_blocks = (n_total * 8 + TB - 1) / TB;
    spmm_kernel<<<spmm_blocks, TB>>>((const uint4*)h1, (uint4*)h2,
                                     col, vals, tedge, u_ptr, i_ptr,
                                     n_users, 0, n_total);
    spmm_final_kernel<<<spmm_blocks, TB>>>((const uint4*)h2, (const uint4*)x0h,
                                           (const uint4*)h1, (float4*)out,
                                           col, vals, tedge, u_ptr, i_ptr,
                                           n_users, n_total);
}